// round 1
// baseline (speedup 1.0000x reference)
#include <cuda_runtime.h>
#include <cuda_bf16.h>
#include <cstddef>

// Problem constants
#define BB 8
#define TT 16
#define HH 64
#define WW 64
#define CIN 32
#define FF 32
#define G4F 128        // 4*F gate channels
#define BN_EPS 1e-3f

// smem layout constants
#define SIN_STRIDE 325             // 18*18=324, padded to odd for conflict-free channel stride
#define SIN_FLOATS (32 * SIN_STRIDE)   // 10400 floats
#define SW_FLOATS  (288 * 32)          // 9216 floats
#define SMEM_BYTES ((SIN_FLOATS + SW_FLOATS) * 4)  // 78464 bytes

// Scratch (allocation-free: static __device__ globals)
__device__ float g_xg[(size_t)BB * TT * HH * WW * G4F];  // 268 MB
__device__ float g_h[2][(size_t)BB * HH * WW * FF];      // ping-pong h state
__device__ float g_c[(size_t)BB * HH * WW * FF];

__device__ __forceinline__ float hsig(float x) {
    return __saturatef(fmaf(0.2f, x, 0.5f));
}

// ---------------------------------------------------------------------------
// Kernel 1: xg = conv(x, Wx) + b over all B*T frames.
// grid: (16 tiles, 4 cout-chunks, 128 frames), block: 256 (16x16 pixels)
// ---------------------------------------------------------------------------
__global__ void __launch_bounds__(256) xg_conv_kernel(
    const float* __restrict__ x, const float* __restrict__ Wx,
    const float* __restrict__ b)
{
    extern __shared__ float sm[];
    float* s_in = sm;                 // [32][SIN_STRIDE]
    float* s_w  = sm + SIN_FLOATS;    // [288][32]

    const int tile = blockIdx.x;      // 0..15
    const int cc   = blockIdx.y;      // cout chunk 0..3
    const int n    = blockIdx.z;      // frame 0..127  (n = b*T + t)
    const int ty0 = (tile >> 2) * 16;
    const int tx0 = (tile & 3) * 16;
    const int tid = threadIdx.x;

    // load 18x18x32 input tile (channel-major smem, coalesced gmem)
    const float* xin = x + (size_t)n * HH * WW * CIN;
    for (int i = tid; i < 18 * 18 * 32; i += 256) {
        int cin = i & 31;
        int p   = i >> 5;             // 0..323
        int py  = p / 18, px = p - py * 18;
        int gy = ty0 + py - 1, gx = tx0 + px - 1;
        float v = 0.f;
        if ((unsigned)gy < (unsigned)HH && (unsigned)gx < (unsigned)WW)
            v = xin[((size_t)gy * WW + gx) * CIN + cin];
        s_in[cin * SIN_STRIDE + p] = v;
    }
    // load weight chunk: 288 taps x 32 couts
    for (int i = tid; i < 288 * 32; i += 256) {
        int k = i >> 5, co = i & 31;
        s_w[i] = Wx[k * G4F + cc * 32 + co];
    }
    __syncthreads();

    const int py = tid >> 4, px = tid & 15;
    float acc[32];
#pragma unroll
    for (int co = 0; co < 32; co++) acc[co] = 0.f;

#pragma unroll
    for (int dy = 0; dy < 3; dy++) {
#pragma unroll
        for (int dx = 0; dx < 3; dx++) {
            const float* inb = &s_in[(py + dy) * 18 + (px + dx)];
            const float* wb  = &s_w[(dy * 3 + dx) * 32 * 32];
#pragma unroll 4
            for (int cin = 0; cin < 32; cin++) {
                float v = inb[cin * SIN_STRIDE];
                const float4* w4 = (const float4*)(wb + cin * 32);
#pragma unroll
                for (int q = 0; q < 8; q++) {
                    float4 w = w4[q];
                    acc[q * 4 + 0] = fmaf(v, w.x, acc[q * 4 + 0]);
                    acc[q * 4 + 1] = fmaf(v, w.y, acc[q * 4 + 1]);
                    acc[q * 4 + 2] = fmaf(v, w.z, acc[q * 4 + 2]);
                    acc[q * 4 + 3] = fmaf(v, w.w, acc[q * 4 + 3]);
                }
            }
        }
    }

    const int gy = ty0 + py, gx = tx0 + px;
    float* outp = &g_xg[(((size_t)n * HH * WW) + (size_t)gy * WW + gx) * G4F + cc * 32];
#pragma unroll
    for (int q = 0; q < 8; q++) {
        float4 bv = *(const float4*)&b[cc * 32 + q * 4];
        float4 o;
        o.x = acc[q * 4 + 0] + bv.x;
        o.y = acc[q * 4 + 1] + bv.y;
        o.z = acc[q * 4 + 2] + bv.z;
        o.w = acc[q * 4 + 3] + bv.w;
        ((float4*)outp)[q] = o;
    }
}

// ---------------------------------------------------------------------------
// Kernel 2: one LSTM timestep, fused: g = xg_t + conv(h_{t-1}, Wh); gates;
// c,h update; BatchNorm affine; output write.
// grid: (16 tiles, 4 f-chunks of 8 channels, 8 batches), block 256.
// Each thread: 1 pixel, 8 f-channels -> 32 gate accumulators arranged
// acc[g*8 + j] for gate g in {i,f,c,o}, channel f = fc*8 + j.
// ---------------------------------------------------------------------------
__global__ void __launch_bounds__(256) lstm_step_kernel(
    const float* __restrict__ Wh,
    const float* __restrict__ gamma, const float* __restrict__ beta,
    const float* __restrict__ mmean, const float* __restrict__ mvar,
    float* __restrict__ out, int t)
{
    extern __shared__ float sm[];
    float* s_in = sm;
    float* s_w  = sm + SIN_FLOATS;

    const int tile = blockIdx.x;      // 0..15
    const int fc   = blockIdx.y;      // f-chunk 0..3 (8 channels each)
    const int bb   = blockIdx.z;      // batch
    const int ty0 = (tile >> 2) * 16;
    const int tx0 = (tile & 3) * 16;
    const int tid = threadIdx.x;

    if (t > 0) {
        // read h_{t-1} from ping-pong buffer (t-1)&1
        const float* hin = g_h[(t + 1) & 1] + (size_t)bb * HH * WW * FF;
        for (int i = tid; i < 18 * 18 * 32; i += 256) {
            int cin = i & 31;
            int p   = i >> 5;
            int py  = p / 18, px = p - py * 18;
            int gy = ty0 + py - 1, gx = tx0 + px - 1;
            float v = 0.f;
            if ((unsigned)gy < (unsigned)HH && (unsigned)gx < (unsigned)WW)
                v = hin[((size_t)gy * WW + gx) * FF + cin];
            s_in[cin * SIN_STRIDE + p] = v;
        }
        // weight chunk: col = g*8+j  ->  cout = g*32 + fc*8 + j
        for (int i = tid; i < 288 * 32; i += 256) {
            int k = i >> 5, col = i & 31;
            int cout = (col >> 3) * 32 + fc * 8 + (col & 7);
            s_w[i] = Wh[k * G4F + cout];
        }
        __syncthreads();
    }

    float acc[32];
#pragma unroll
    for (int co = 0; co < 32; co++) acc[co] = 0.f;

    const int py = tid >> 4, px = tid & 15;

    if (t > 0) {
#pragma unroll
        for (int dy = 0; dy < 3; dy++) {
#pragma unroll
            for (int dx = 0; dx < 3; dx++) {
                const float* inb = &s_in[(py + dy) * 18 + (px + dx)];
                const float* wb  = &s_w[(dy * 3 + dx) * 32 * 32];
#pragma unroll 4
                for (int cin = 0; cin < 32; cin++) {
                    float v = inb[cin * SIN_STRIDE];
                    const float4* w4 = (const float4*)(wb + cin * 32);
#pragma unroll
                    for (int q = 0; q < 8; q++) {
                        float4 w = w4[q];
                        acc[q * 4 + 0] = fmaf(v, w.x, acc[q * 4 + 0]);
                        acc[q * 4 + 1] = fmaf(v, w.y, acc[q * 4 + 1]);
                        acc[q * 4 + 2] = fmaf(v, w.z, acc[q * 4 + 2]);
                        acc[q * 4 + 3] = fmaf(v, w.w, acc[q * 4 + 3]);
                    }
                }
            }
        }
    }

    const int gy = ty0 + py, gx = tx0 + px;
    const size_t pix   = (size_t)bb * HH * WW + (size_t)gy * WW + gx;
    const size_t frame = (size_t)(bb * TT + t) * HH * WW + (size_t)gy * WW + gx;
    const float* xgp = &g_xg[frame * G4F];
    float* cst = &g_c[pix * FF + fc * 8];
    float* hst = &g_h[t & 1][pix * FF + fc * 8];
    float* op  = &out[frame * FF + fc * 8];

#pragma unroll
    for (int j = 0; j < 8; j++) {
        int f = fc * 8 + j;
        float gi = acc[0 * 8 + j] + xgp[0 * 32 + f];
        float gf = acc[1 * 8 + j] + xgp[1 * 32 + f];
        float gc = acc[2 * 8 + j] + xgp[2 * 32 + f];
        float go = acc[3 * 8 + j] + xgp[3 * 32 + f];
        gi = hsig(gi); gf = hsig(gf); go = hsig(go);
        float cold = (t > 0) ? cst[j] : 0.f;
        float cn = gf * cold + gi * tanhf(gc);
        float h  = go * tanhf(cn);
        cst[j] = cn;
        hst[j] = h;
        float inv = gamma[f] * rsqrtf(mvar[f] + BN_EPS);
        op[j] = fmaf(h, inv, beta[f] - mmean[f] * inv);
    }
}

// ---------------------------------------------------------------------------
extern "C" void kernel_launch(void* const* d_in, const int* in_sizes, int n_in,
                              void* d_out, int out_size)
{
    const float* x     = (const float*)d_in[0];
    const float* Wx    = (const float*)d_in[1];
    const float* Wh    = (const float*)d_in[2];
    const float* b     = (const float*)d_in[3];
    const float* gamma = (const float*)d_in[4];
    const float* beta  = (const float*)d_in[5];
    const float* mmean = (const float*)d_in[6];
    const float* mvar  = (const float*)d_in[7];
    float* out = (float*)d_out;

    cudaFuncSetAttribute(xg_conv_kernel,
        cudaFuncAttributeMaxDynamicSharedMemorySize, SMEM_BYTES);
    cudaFuncSetAttribute(lstm_step_kernel,
        cudaFuncAttributeMaxDynamicSharedMemorySize, SMEM_BYTES);

    // 1) input-to-gate conv for all frames
    {
        dim3 grid(16, 4, BB * TT);
        xg_conv_kernel<<<grid, 256, SMEM_BYTES>>>(x, Wx, b);
    }
    // 2) sequential recurrence
    for (int t = 0; t < TT; t++) {
        dim3 grid(16, 4, BB);
        lstm_step_kernel<<<grid, 256, SMEM_BYTES>>>(
            Wh, gamma, beta, mmean, mvar, out, t);
    }
}

// round 2
// speedup vs baseline: 1.1954x; 1.1954x over previous
#include <cuda_runtime.h>
#include <cuda_bf16.h>
#include <cstddef>

// Problem constants
#define BB 8
#define TT 16
#define HH 64
#define WW 64
#define CIN 32
#define FF 32
#define G4F 128        // 4*F gate channels
#define BN_EPS 1e-3f

// smem layout constants
#define SIN_STRIDE 325             // 18*18=324, padded to odd for conflict-free channel stride
#define SIN_FLOATS (32 * SIN_STRIDE)   // 10400 floats
#define SW_FLOATS  (288 * 32)          // 9216 floats
#define SMEM_BYTES ((SIN_FLOATS + SW_FLOATS) * 4)  // 78464 bytes

// Scratch (allocation-free: static __device__ globals)
__device__ float g_xg[(size_t)BB * TT * HH * WW * G4F];  // 268 MB
__device__ float g_h[2][(size_t)BB * HH * WW * FF];      // ping-pong h state
__device__ float g_c[(size_t)BB * HH * WW * FF];

__device__ __forceinline__ float hsig(float x) {
    return __saturatef(fmaf(0.2f, x, 0.5f));
}

// ---- packed f32x2 helpers (sm_103a: doubles fp32 FMA throughput) ----
__device__ __forceinline__ unsigned long long pack2(float v) {
    unsigned long long r;
    asm("mov.b64 %0, {%1, %1};" : "=l"(r) : "f"(v));
    return r;
}
__device__ __forceinline__ void ffma2(unsigned long long& d,
                                      unsigned long long a,
                                      unsigned long long b) {
    asm("fma.rn.f32x2 %0, %1, %2, %3;" : "=l"(d) : "l"(a), "l"(b), "l"(d));
}
__device__ __forceinline__ void unpack2(unsigned long long p, float& lo, float& hi) {
    asm("mov.b64 {%0, %1}, %2;" : "=f"(lo), "=f"(hi) : "l"(p));
}

// ---------------------------------------------------------------------------
// Kernel 1: xg = conv(x, Wx) + b over all B*T frames.
// grid: (16 tiles, 4 cout-chunks, 128 frames), block: 256 (16x16 pixels)
// ---------------------------------------------------------------------------
__global__ void __launch_bounds__(256) xg_conv_kernel(
    const float* __restrict__ x, const float* __restrict__ Wx,
    const float* __restrict__ b)
{
    extern __shared__ float sm[];
    float* s_in = sm;                 // [32][SIN_STRIDE]
    float* s_w  = sm + SIN_FLOATS;    // [288][32]

    const int tile = blockIdx.x;      // 0..15
    const int cc   = blockIdx.y;      // cout chunk 0..3
    const int n    = blockIdx.z;      // frame 0..127  (n = b*T + t)
    const int ty0 = (tile >> 2) * 16;
    const int tx0 = (tile & 3) * 16;
    const int tid = threadIdx.x;

    // load 18x18x32 input tile (channel-major smem, coalesced gmem)
    const float* xin = x + (size_t)n * HH * WW * CIN;
    for (int i = tid; i < 18 * 18 * 32; i += 256) {
        int cin = i & 31;
        int p   = i >> 5;             // 0..323
        int py  = p / 18, px = p - py * 18;
        int gy = ty0 + py - 1, gx = tx0 + px - 1;
        float v = 0.f;
        if ((unsigned)gy < (unsigned)HH && (unsigned)gx < (unsigned)WW)
            v = xin[((size_t)gy * WW + gx) * CIN + cin];
        s_in[cin * SIN_STRIDE + p] = v;
    }
    // load weight chunk: 288 taps x 32 couts
    for (int i = tid; i < 288 * 32; i += 256) {
        int k = i >> 5, co = i & 31;
        s_w[i] = Wx[k * G4F + cc * 32 + co];
    }
    __syncthreads();

    const int py = tid >> 4, px = tid & 15;
    unsigned long long acc[16];       // 16 x f32x2 = 32 couts
#pragma unroll
    for (int m = 0; m < 16; m++) acc[m] = 0ull;

#pragma unroll
    for (int dy = 0; dy < 3; dy++) {
#pragma unroll
        for (int dx = 0; dx < 3; dx++) {
            const float* inb = &s_in[(py + dy) * 18 + (px + dx)];
            const float* wb  = &s_w[(dy * 3 + dx) * 32 * 32];
#pragma unroll 4
            for (int cin = 0; cin < 32; cin++) {
                unsigned long long vv = pack2(inb[cin * SIN_STRIDE]);
                const ulonglong2* w2 = (const ulonglong2*)(wb + cin * 32);
#pragma unroll
                for (int q = 0; q < 8; q++) {
                    ulonglong2 w = w2[q];
                    ffma2(acc[q * 2 + 0], vv, w.x);
                    ffma2(acc[q * 2 + 1], vv, w.y);
                }
            }
        }
    }

    float a[32];
#pragma unroll
    for (int m = 0; m < 16; m++) unpack2(acc[m], a[2 * m], a[2 * m + 1]);

    const int gy = ty0 + py, gx = tx0 + px;
    float* outp = &g_xg[(((size_t)n * HH * WW) + (size_t)gy * WW + gx) * G4F + cc * 32];
#pragma unroll
    for (int q = 0; q < 8; q++) {
        float4 bv = *(const float4*)&b[cc * 32 + q * 4];
        float4 o;
        o.x = a[q * 4 + 0] + bv.x;
        o.y = a[q * 4 + 1] + bv.y;
        o.z = a[q * 4 + 2] + bv.z;
        o.w = a[q * 4 + 3] + bv.w;
        ((float4*)outp)[q] = o;
    }
}

// ---------------------------------------------------------------------------
// Kernel 2: one LSTM timestep, fused: g = xg_t + conv(h_{t-1}, Wh); gates;
// c,h update; BatchNorm affine; output write.
// grid: (16 tiles, 4 f-chunks of 8 channels, 8 batches), block 256.
// acc pair m covers cols (2m, 2m+1); col = g*8+j maps to gate g, channel fc*8+j.
// ---------------------------------------------------------------------------
__global__ void __launch_bounds__(256) lstm_step_kernel(
    const float* __restrict__ Wh,
    const float* __restrict__ gamma, const float* __restrict__ beta,
    const float* __restrict__ mmean, const float* __restrict__ mvar,
    float* __restrict__ out, int t)
{
    extern __shared__ float sm[];
    float* s_in = sm;
    float* s_w  = sm + SIN_FLOATS;

    const int tile = blockIdx.x;      // 0..15
    const int fc   = blockIdx.y;      // f-chunk 0..3 (8 channels each)
    const int bb   = blockIdx.z;      // batch
    const int ty0 = (tile >> 2) * 16;
    const int tx0 = (tile & 3) * 16;
    const int tid = threadIdx.x;

    if (t > 0) {
        // read h_{t-1} from ping-pong buffer (t-1)&1
        const float* hin = g_h[(t + 1) & 1] + (size_t)bb * HH * WW * FF;
        for (int i = tid; i < 18 * 18 * 32; i += 256) {
            int cin = i & 31;
            int p   = i >> 5;
            int py  = p / 18, px = p - py * 18;
            int gy = ty0 + py - 1, gx = tx0 + px - 1;
            float v = 0.f;
            if ((unsigned)gy < (unsigned)HH && (unsigned)gx < (unsigned)WW)
                v = hin[((size_t)gy * WW + gx) * FF + cin];
            s_in[cin * SIN_STRIDE + p] = v;
        }
        // weight chunk: col = g*8+j  ->  cout = g*32 + fc*8 + j
        for (int i = tid; i < 288 * 32; i += 256) {
            int k = i >> 5, col = i & 31;
            int cout = (col >> 3) * 32 + fc * 8 + (col & 7);
            s_w[i] = Wh[k * G4F + cout];
        }
        __syncthreads();
    }

    unsigned long long acc[16];
#pragma unroll
    for (int m = 0; m < 16; m++) acc[m] = 0ull;

    const int py = tid >> 4, px = tid & 15;

    if (t > 0) {
#pragma unroll
        for (int dy = 0; dy < 3; dy++) {
#pragma unroll
            for (int dx = 0; dx < 3; dx++) {
                const float* inb = &s_in[(py + dy) * 18 + (px + dx)];
                const float* wb  = &s_w[(dy * 3 + dx) * 32 * 32];
#pragma unroll 4
                for (int cin = 0; cin < 32; cin++) {
                    unsigned long long vv = pack2(inb[cin * SIN_STRIDE]);
                    const ulonglong2* w2 = (const ulonglong2*)(wb + cin * 32);
#pragma unroll
                    for (int q = 0; q < 8; q++) {
                        ulonglong2 w = w2[q];
                        ffma2(acc[q * 2 + 0], vv, w.x);
                        ffma2(acc[q * 2 + 1], vv, w.y);
                    }
                }
            }
        }
    }

    float a[32];
#pragma unroll
    for (int m = 0; m < 16; m++) unpack2(acc[m], a[2 * m], a[2 * m + 1]);

    const int gy = ty0 + py, gx = tx0 + px;
    const size_t pix   = (size_t)bb * HH * WW + (size_t)gy * WW + gx;
    const size_t frame = (size_t)(bb * TT + t) * HH * WW + (size_t)gy * WW + gx;
    const float* xgp = &g_xg[frame * G4F];
    float* cst = &g_c[pix * FF + fc * 8];
    float* hst = &g_h[t & 1][pix * FF + fc * 8];
    float* op  = &out[frame * FF + fc * 8];

    float cv[8], hv[8], ov[8];
    float4 cold0 = make_float4(0.f, 0.f, 0.f, 0.f), cold1 = cold0;
    if (t > 0) {
        cold0 = ((const float4*)cst)[0];
        cold1 = ((const float4*)cst)[1];
    }
    float coldv[8] = {cold0.x, cold0.y, cold0.z, cold0.w,
                      cold1.x, cold1.y, cold1.z, cold1.w};

#pragma unroll
    for (int j = 0; j < 8; j++) {
        int f = fc * 8 + j;
        float gi = a[0 * 8 + j] + xgp[0 * 32 + f];
        float gf = a[1 * 8 + j] + xgp[1 * 32 + f];
        float gc = a[2 * 8 + j] + xgp[2 * 32 + f];
        float go = a[3 * 8 + j] + xgp[3 * 32 + f];
        gi = hsig(gi); gf = hsig(gf); go = hsig(go);
        float cn = gf * coldv[j] + gi * tanhf(gc);
        float h  = go * tanhf(cn);
        cv[j] = cn;
        hv[j] = h;
        float inv = gamma[f] * rsqrtf(mvar[f] + BN_EPS);
        ov[j] = fmaf(h, inv, beta[f] - mmean[f] * inv);
    }
    ((float4*)cst)[0] = make_float4(cv[0], cv[1], cv[2], cv[3]);
    ((float4*)cst)[1] = make_float4(cv[4], cv[5], cv[6], cv[7]);
    ((float4*)hst)[0] = make_float4(hv[0], hv[1], hv[2], hv[3]);
    ((float4*)hst)[1] = make_float4(hv[4], hv[5], hv[6], hv[7]);
    ((float4*)op)[0]  = make_float4(ov[0], ov[1], ov[2], ov[3]);
    ((float4*)op)[1]  = make_float4(ov[4], ov[5], ov[6], ov[7]);
}

// ---------------------------------------------------------------------------
extern "C" void kernel_launch(void* const* d_in, const int* in_sizes, int n_in,
                              void* d_out, int out_size)
{
    const float* x     = (const float*)d_in[0];
    const float* Wx    = (const float*)d_in[1];
    const float* Wh    = (const float*)d_in[2];
    const float* b     = (const float*)d_in[3];
    const float* gamma = (const float*)d_in[4];
    const float* beta  = (const float*)d_in[5];
    const float* mmean = (const float*)d_in[6];
    const float* mvar  = (const float*)d_in[7];
    float* out = (float*)d_out;

    cudaFuncSetAttribute(xg_conv_kernel,
        cudaFuncAttributeMaxDynamicSharedMemorySize, SMEM_BYTES);
    cudaFuncSetAttribute(lstm_step_kernel,
        cudaFuncAttributeMaxDynamicSharedMemorySize, SMEM_BYTES);

    // 1) input-to-gate conv for all frames
    {
        dim3 grid(16, 4, BB * TT);
        xg_conv_kernel<<<grid, 256, SMEM_BYTES>>>(x, Wx, b);
    }
    // 2) sequential recurrence
    for (int t = 0; t < TT; t++) {
        dim3 grid(16, 4, BB);
        lstm_step_kernel<<<grid, 256, SMEM_BYTES>>>(
            Wh, gamma, beta, mmean, mvar, out, t);
    }
}

// round 3
// speedup vs baseline: 1.5513x; 1.2978x over previous
#include <cuda_runtime.h>
#include <cuda_bf16.h>
#include <cstddef>

// Problem constants
#define BB 8
#define TT 16
#define HH 64
#define WW 64
#define CIN 32
#define FF 32
#define G4F 128
#define BN_EPS 1e-3f

// Tile: 32 wide x 16 tall, 256 threads, 2 pixels/thread (rows pr, pr+8)
#define TW 32
#define TH 16
#define IN_ROWS 18           // TH + 2
#define IN_COLS 34           // TW + 2
#define ROW_STRIDE (32 * IN_COLS)        // [row][cin][col], 1088 floats
#define SIN_FLOATS (IN_ROWS * ROW_STRIDE)  // 19584
#define SW_FLOATS  (288 * 32)              // 9216
#define SMEM_BYTES ((SIN_FLOATS + SW_FLOATS) * 4)  // 115200 B

// Scratch (allocation-free: static __device__ globals)
__device__ float g_xg[(size_t)BB * TT * HH * WW * G4F];
__device__ float g_h[2][(size_t)BB * HH * WW * FF];
__device__ float g_c[(size_t)BB * HH * WW * FF];

__device__ __forceinline__ float hsig(float x) {
    return __saturatef(fmaf(0.2f, x, 0.5f));
}

// ---- packed f32x2 helpers ----
__device__ __forceinline__ unsigned long long pack2(float v) {
    unsigned long long r;
    asm("mov.b64 %0, {%1, %1};" : "=l"(r) : "f"(v));
    return r;
}
__device__ __forceinline__ void ffma2(unsigned long long& d,
                                      unsigned long long a,
                                      unsigned long long b) {
    asm("fma.rn.f32x2 %0, %1, %2, %3;" : "=l"(d) : "l"(a), "l"(b), "l"(d));
}
__device__ __forceinline__ void unpack2(unsigned long long p, float& lo, float& hi) {
    asm("mov.b64 {%0, %1}, %2;" : "=f"(lo), "=f"(hi) : "l"(p));
}

// Shared conv core: loads input tile + weights assumed already in smem.
// Computes 32 couts for 2 pixels. Returns via acc arrays.
__device__ __forceinline__ void conv_core(
    const float* __restrict__ s_in, const float* __restrict__ s_w,
    int pr, int px, unsigned long long* acc0, unsigned long long* acc1)
{
#pragma unroll
    for (int dy = 0; dy < 3; dy++) {
#pragma unroll
        for (int dx = 0; dx < 3; dx++) {
            const float* i0 = &s_in[(pr + dy) * ROW_STRIDE + (px + dx)];
            const float* i1 = i0 + 8 * ROW_STRIDE;
            const float* wb = &s_w[(dy * 3 + dx) * 32 * 32];
#pragma unroll 4
            for (int cin = 0; cin < 32; cin++) {
                unsigned long long v0 = pack2(i0[cin * IN_COLS]);
                unsigned long long v1 = pack2(i1[cin * IN_COLS]);
                const ulonglong2* w2 = (const ulonglong2*)(wb + cin * 32);
#pragma unroll
                for (int q = 0; q < 8; q++) {
                    ulonglong2 w = w2[q];
                    ffma2(acc0[q * 2 + 0], v0, w.x);
                    ffma2(acc0[q * 2 + 1], v0, w.y);
                    ffma2(acc1[q * 2 + 0], v1, w.x);
                    ffma2(acc1[q * 2 + 1], v1, w.y);
                }
            }
        }
    }
}

// Load 18x34x32 input tile into smem, layout [row][cin][col]
__device__ __forceinline__ void load_input_tile(
    float* __restrict__ s_in, const float* __restrict__ src,
    int ty0, int tx0, int tid, int ch_stride)
{
    for (int i = tid; i < IN_ROWS * IN_COLS * 32; i += 256) {
        int cin = i & 31;
        int p   = i >> 5;
        int row = p / IN_COLS, col = p - row * IN_COLS;
        int gy = ty0 + row - 1, gx = tx0 + col - 1;
        float v = 0.f;
        if ((unsigned)gy < (unsigned)HH && (unsigned)gx < (unsigned)WW)
            v = src[((size_t)gy * WW + gx) * ch_stride + cin];
        s_in[(row * 32 + cin) * IN_COLS + col] = v;
    }
}

// ---------------------------------------------------------------------------
// Kernel 1: xg = conv(x, Wx) + b over all B*T frames.
// grid: (8 tiles, 4 cout-chunks, 128 frames), block 256, 2 px/thread
// ---------------------------------------------------------------------------
__global__ void __launch_bounds__(256, 2) xg_conv_kernel(
    const float* __restrict__ x, const float* __restrict__ Wx,
    const float* __restrict__ b)
{
    extern __shared__ float sm[];
    float* s_in = sm;
    float* s_w  = sm + SIN_FLOATS;

    const int tile = blockIdx.x;       // 0..7: tx = tile&1, ty = tile>>1
    const int cc   = blockIdx.y;       // cout chunk 0..3
    const int n    = blockIdx.z;       // frame
    const int tx0 = (tile & 1) * TW;
    const int ty0 = (tile >> 1) * TH;
    const int tid = threadIdx.x;

    load_input_tile(s_in, x + (size_t)n * HH * WW * CIN, ty0, tx0, tid, CIN);
    for (int i = tid; i < 288 * 32; i += 256) {
        int k = i >> 5, co = i & 31;
        s_w[i] = Wx[k * G4F + cc * 32 + co];
    }
    __syncthreads();

    const int px = tid & 31, pr = tid >> 5;
    unsigned long long acc0[16], acc1[16];
#pragma unroll
    for (int m = 0; m < 16; m++) { acc0[m] = 0ull; acc1[m] = 0ull; }

    conv_core(s_in, s_w, pr, px, acc0, acc1);

    float a0[32], a1[32];
#pragma unroll
    for (int m = 0; m < 16; m++) {
        unpack2(acc0[m], a0[2 * m], a0[2 * m + 1]);
        unpack2(acc1[m], a1[2 * m], a1[2 * m + 1]);
    }

    const int gx = tx0 + px;
    const int gy0 = ty0 + pr, gy1 = gy0 + 8;
    float* o0 = &g_xg[(((size_t)n * HH + gy0) * WW + gx) * G4F + cc * 32];
    float* o1 = &g_xg[(((size_t)n * HH + gy1) * WW + gx) * G4F + cc * 32];
#pragma unroll
    for (int q = 0; q < 8; q++) {
        float4 bv = *(const float4*)&b[cc * 32 + q * 4];
        ((float4*)o0)[q] = make_float4(a0[q*4+0]+bv.x, a0[q*4+1]+bv.y,
                                       a0[q*4+2]+bv.z, a0[q*4+3]+bv.w);
        ((float4*)o1)[q] = make_float4(a1[q*4+0]+bv.x, a1[q*4+1]+bv.y,
                                       a1[q*4+2]+bv.z, a1[q*4+3]+bv.w);
    }
}

// ---------------------------------------------------------------------------
// Kernel 2: one LSTM timestep, fully fused. grid: (8,4,8), block 256.
// Weight cols interleave gates: col = g*8 + j -> cout = g*32 + fc*8 + j
// ---------------------------------------------------------------------------
__global__ void __launch_bounds__(256, 2) lstm_step_kernel(
    const float* __restrict__ Wh,
    const float* __restrict__ gamma, const float* __restrict__ beta,
    const float* __restrict__ mmean, const float* __restrict__ mvar,
    float* __restrict__ out, int t)
{
    extern __shared__ float sm[];
    float* s_in = sm;
    float* s_w  = sm + SIN_FLOATS;

    const int tile = blockIdx.x;
    const int fc   = blockIdx.y;       // f-chunk 0..3 (8 channels)
    const int bb   = blockIdx.z;
    const int tx0 = (tile & 1) * TW;
    const int ty0 = (tile >> 1) * TH;
    const int tid = threadIdx.x;

    if (t > 0) {
        const float* hin = g_h[(t + 1) & 1] + (size_t)bb * HH * WW * FF;
        load_input_tile(s_in, hin, ty0, tx0, tid, FF);
        for (int i = tid; i < 288 * 32; i += 256) {
            int k = i >> 5, col = i & 31;
            int cout = (col >> 3) * 32 + fc * 8 + (col & 7);
            s_w[i] = Wh[k * G4F + cout];
        }
        __syncthreads();
    }

    unsigned long long acc0[16], acc1[16];
#pragma unroll
    for (int m = 0; m < 16; m++) { acc0[m] = 0ull; acc1[m] = 0ull; }

    const int px = tid & 31, pr = tid >> 5;

    if (t > 0)
        conv_core(s_in, s_w, pr, px, acc0, acc1);

    float a0[32], a1[32];
#pragma unroll
    for (int m = 0; m < 16; m++) {
        unpack2(acc0[m], a0[2 * m], a0[2 * m + 1]);
        unpack2(acc1[m], a1[2 * m], a1[2 * m + 1]);
    }

    const int gx = tx0 + px;
    const int gy0 = ty0 + pr;

    // BN constants for this f-chunk (8 channels)
    float inv[8], off[8];
#pragma unroll
    for (int j = 0; j < 8; j++) {
        int f = fc * 8 + j;
        inv[j] = gamma[f] * rsqrtf(mvar[f] + BN_EPS);
        off[j] = beta[f] - mmean[f] * inv[j];
    }

#pragma unroll
    for (int p = 0; p < 2; p++) {
        const float* a = p ? a1 : a0;
        const int gy = gy0 + p * 8;
        const size_t pix   = (size_t)bb * HH * WW + (size_t)gy * WW + gx;
        const size_t frame = (size_t)(bb * TT + t) * HH * WW + (size_t)gy * WW + gx;
        const float* xgp = &g_xg[frame * G4F];
        float* cst = &g_c[pix * FF + fc * 8];
        float* hst = &g_h[t & 1][pix * FF + fc * 8];
        float* op  = &out[frame * FF + fc * 8];

        float coldv[8] = {0,0,0,0,0,0,0,0};
        if (t > 0) {
            float4 c0 = ((const float4*)cst)[0];
            float4 c1 = ((const float4*)cst)[1];
            coldv[0]=c0.x; coldv[1]=c0.y; coldv[2]=c0.z; coldv[3]=c0.w;
            coldv[4]=c1.x; coldv[5]=c1.y; coldv[6]=c1.z; coldv[7]=c1.w;
        }

        float cv[8], hv[8], ov[8];
#pragma unroll
        for (int j = 0; j < 8; j++) {
            int f = fc * 8 + j;
            float gi = a[0 * 8 + j] + xgp[0 * 32 + f];
            float gf = a[1 * 8 + j] + xgp[1 * 32 + f];
            float gc = a[2 * 8 + j] + xgp[2 * 32 + f];
            float go = a[3 * 8 + j] + xgp[3 * 32 + f];
            gi = hsig(gi); gf = hsig(gf); go = hsig(go);
            float cn = gf * coldv[j] + gi * tanhf(gc);
            float h  = go * tanhf(cn);
            cv[j] = cn; hv[j] = h;
            ov[j] = fmaf(h, inv[j], off[j]);
        }
        ((float4*)cst)[0] = make_float4(cv[0], cv[1], cv[2], cv[3]);
        ((float4*)cst)[1] = make_float4(cv[4], cv[5], cv[6], cv[7]);
        ((float4*)hst)[0] = make_float4(hv[0], hv[1], hv[2], hv[3]);
        ((float4*)hst)[1] = make_float4(hv[4], hv[5], hv[6], hv[7]);
        ((float4*)op)[0]  = make_float4(ov[0], ov[1], ov[2], ov[3]);
        ((float4*)op)[1]  = make_float4(ov[4], ov[5], ov[6], ov[7]);
    }
}

// ---------------------------------------------------------------------------
extern "C" void kernel_launch(void* const* d_in, const int* in_sizes, int n_in,
                              void* d_out, int out_size)
{
    const float* x     = (const float*)d_in[0];
    const float* Wx    = (const float*)d_in[1];
    const float* Wh    = (const float*)d_in[2];
    const float* b     = (const float*)d_in[3];
    const float* gamma = (const float*)d_in[4];
    const float* beta  = (const float*)d_in[5];
    const float* mmean = (const float*)d_in[6];
    const float* mvar  = (const float*)d_in[7];
    float* out = (float*)d_out;

    cudaFuncSetAttribute(xg_conv_kernel,
        cudaFuncAttributeMaxDynamicSharedMemorySize, SMEM_BYTES);
    cudaFuncSetAttribute(lstm_step_kernel,
        cudaFuncAttributeMaxDynamicSharedMemorySize, SMEM_BYTES);

    {
        dim3 grid(8, 4, BB * TT);
        xg_conv_kernel<<<grid, 256, SMEM_BYTES>>>(x, Wx, b);
    }
    for (int t = 0; t < TT; t++) {
        dim3 grid(8, 4, BB);
        lstm_step_kernel<<<grid, 256, SMEM_BYTES>>>(
            Wh, gamma, beta, mmean, mvar, out, t);
    }
}

// round 4
// speedup vs baseline: 1.6546x; 1.0666x over previous
#include <cuda_runtime.h>
#include <cuda_bf16.h>
#include <cstddef>

// Problem constants
#define BB 8
#define TT 16
#define HH 64
#define WW 64
#define CIN 32
#define FF 32
#define G4F 128
#define BN_EPS 1e-3f

// Tile: 32 wide x 16 tall, 256 threads, 2 px/thread (rows pr, pr+8)
#define TW 32
#define TH 16
#define IN_ROWS 18
#define IN_COLS 34
#define ROW_STRIDE (32 * IN_COLS)
#define SIN_FLOATS (IN_ROWS * ROW_STRIDE)     // 19584
#define SWBUF_FLOATS (2 * 32 * 32)            // 2048 (double-buffered tap)
#define SMEM_BYTES ((SIN_FLOATS + SWBUF_FLOATS) * 4)  // 86528 B -> 2 CTA/SM

#define LSTM_GRID 256   // 8 tiles * 4 chunks * 8 batch; <= 296 resident

// Scratch (allocation-free: static __device__ globals)
__device__ float g_xg[(size_t)BB * TT * HH * WW * G4F];
__device__ float g_h[2][(size_t)BB * HH * WW * FF];
__device__ float g_c[(size_t)BB * HH * WW * FF];
__device__ unsigned g_bar[TT];   // per-step barrier counters

__device__ __forceinline__ float hsig(float x) {
    return __saturatef(fmaf(0.2f, x, 0.5f));
}

// ---- packed f32x2 helpers ----
__device__ __forceinline__ unsigned long long pack2(float v) {
    unsigned long long r;
    asm("mov.b64 %0, {%1, %1};" : "=l"(r) : "f"(v));
    return r;
}
__device__ __forceinline__ void ffma2(unsigned long long& d,
                                      unsigned long long a,
                                      unsigned long long b) {
    asm("fma.rn.f32x2 %0, %1, %2, %3;" : "=l"(d) : "l"(a), "l"(b), "l"(d));
}
__device__ __forceinline__ void unpack2(unsigned long long p, float& lo, float& hi) {
    asm("mov.b64 {%0, %1}, %2;" : "=f"(lo), "=f"(hi) : "l"(p));
}

// Compute one 3x3 tap (dy,dx) over 32 cin for 2 pixels, 32 couts.
__device__ __forceinline__ void conv_tap(
    const float* __restrict__ s_in, const float* __restrict__ wb,
    int pr, int px, int dy, int dx,
    unsigned long long* acc0, unsigned long long* acc1)
{
    const float* i0 = &s_in[(pr + dy) * ROW_STRIDE + (px + dx)];
    const float* i1 = i0 + 8 * ROW_STRIDE;
#pragma unroll 4
    for (int cin = 0; cin < 32; cin++) {
        unsigned long long v0 = pack2(i0[cin * IN_COLS]);
        unsigned long long v1 = pack2(i1[cin * IN_COLS]);
        const ulonglong2* w2 = (const ulonglong2*)(wb + cin * 32);
#pragma unroll
        for (int q = 0; q < 8; q++) {
            ulonglong2 w = w2[q];
            ffma2(acc0[q * 2 + 0], v0, w.x);
            ffma2(acc0[q * 2 + 1], v0, w.y);
            ffma2(acc1[q * 2 + 0], v1, w.x);
            ffma2(acc1[q * 2 + 1], v1, w.y);
        }
    }
}

// Tap weight loaders: 32cin x 32cols = 1024 floats, 1 float4 per thread.
__device__ __forceinline__ void load_tap_xg(
    float* __restrict__ dst, const float* __restrict__ Wx, int kk, int cc, int tid)
{
    int cin = tid >> 3, col0 = (tid & 7) * 4;
    float4 w = *(const float4*)&Wx[((size_t)(kk * CIN + cin)) * G4F + cc * 32 + col0];
    *(float4*)&dst[cin * 32 + col0] = w;
}
__device__ __forceinline__ void load_tap_lstm(
    float* __restrict__ dst, const float* __restrict__ Wh, int kk, int fc, int tid)
{
    int cin = tid >> 3, col0 = (tid & 7) * 4;
    int cout0 = (col0 >> 3) * 32 + fc * 8 + (col0 & 7);  // gate-interleaved
    float4 w = *(const float4*)&Wh[((size_t)(kk * CIN + cin)) * G4F + cout0];
    *(float4*)&dst[cin * 32 + col0] = w;
}

// Load 18x34x32 input tile into smem [row][cin][col].
template <bool CV>
__device__ __forceinline__ void load_input_tile(
    float* __restrict__ s_in, const float* __restrict__ src,
    int ty0, int tx0, int tid, int ch_stride)
{
    for (int i = tid; i < IN_ROWS * IN_COLS * 32; i += 256) {
        int cin = i & 31;
        int p   = i >> 5;
        int row = p / IN_COLS, col = p - row * IN_COLS;
        int gy = ty0 + row - 1, gx = tx0 + col - 1;
        float v = 0.f;
        if ((unsigned)gy < (unsigned)HH && (unsigned)gx < (unsigned)WW) {
            const float* ap = &src[((size_t)gy * WW + gx) * ch_stride + cin];
            v = CV ? __ldcv(ap) : __ldg(ap);
        }
        s_in[(row * 32 + cin) * IN_COLS + col] = v;
    }
}

// ---------------------------------------------------------------------------
// Kernel 1: xg = conv(x, Wx) + b, all frames. grid (8,4,128), block 256.
// ---------------------------------------------------------------------------
__global__ void __launch_bounds__(256, 2) xg_conv_kernel(
    const float* __restrict__ x, const float* __restrict__ Wx,
    const float* __restrict__ b)
{
    extern __shared__ float sm[];
    float* s_in = sm;
    float* s_w  = sm + SIN_FLOATS;   // 2 buffers of 1024 floats

    const int tile = blockIdx.x;
    const int cc   = blockIdx.y;
    const int n    = blockIdx.z;
    const int tx0 = (tile & 1) * TW;
    const int ty0 = (tile >> 1) * TH;
    const int tid = threadIdx.x;

    load_input_tile<false>(s_in, x + (size_t)n * HH * WW * CIN, ty0, tx0, tid, CIN);
    load_tap_xg(s_w, Wx, 0, cc, tid);
    __syncthreads();

    const int px = tid & 31, pr = tid >> 5;
    unsigned long long acc0[16], acc1[16];
#pragma unroll
    for (int m = 0; m < 16; m++) { acc0[m] = 0ull; acc1[m] = 0ull; }

#pragma unroll
    for (int tap = 0; tap < 9; tap++) {
        if (tap < 8)
            load_tap_xg(&s_w[((tap + 1) & 1) * 1024], Wx, tap + 1, cc, tid);
        conv_tap(s_in, &s_w[(tap & 1) * 1024], pr, px, tap / 3, tap % 3, acc0, acc1);
        __syncthreads();
    }

    float a0[32], a1[32];
#pragma unroll
    for (int m = 0; m < 16; m++) {
        unpack2(acc0[m], a0[2 * m], a0[2 * m + 1]);
        unpack2(acc1[m], a1[2 * m], a1[2 * m + 1]);
    }

    const int gx = tx0 + px;
    const int gy0 = ty0 + pr, gy1 = gy0 + 8;
    float* o0 = &g_xg[(((size_t)n * HH + gy0) * WW + gx) * G4F + cc * 32];
    float* o1 = &g_xg[(((size_t)n * HH + gy1) * WW + gx) * G4F + cc * 32];
#pragma unroll
    for (int q = 0; q < 8; q++) {
        float4 bv = *(const float4*)&b[cc * 32 + q * 4];
        ((float4*)o0)[q] = make_float4(a0[q*4+0]+bv.x, a0[q*4+1]+bv.y,
                                       a0[q*4+2]+bv.z, a0[q*4+3]+bv.w);
        ((float4*)o1)[q] = make_float4(a1[q*4+0]+bv.x, a1[q*4+1]+bv.y,
                                       a1[q*4+2]+bv.z, a1[q*4+3]+bv.w);
    }
}

// ---------------------------------------------------------------------------
// Barrier counter reset (run before each lstm_persistent execution)
// ---------------------------------------------------------------------------
__global__ void bar_reset_kernel() {
    if (threadIdx.x < TT) g_bar[threadIdx.x] = 0u;
}

// ---------------------------------------------------------------------------
// Kernel 2: persistent LSTM — all 16 timesteps in one launch, software
// grid barrier between steps. grid = 256 CTAs (all resident @ 2 CTA/SM).
// CTA: tile(8) x f-chunk(4) x batch(8). Thread: 2 px, 8 channels, 4 gates.
// ---------------------------------------------------------------------------
__global__ void __launch_bounds__(256, 2) lstm_persistent(
    const float* __restrict__ Wh,
    const float* __restrict__ gamma, const float* __restrict__ beta,
    const float* __restrict__ mmean, const float* __restrict__ mvar,
    float* __restrict__ out)
{
    extern __shared__ float sm[];
    float* s_in = sm;
    float* s_w  = sm + SIN_FLOATS;

    const int cta  = blockIdx.x;          // 0..255
    const int tile = cta & 7;
    const int fc   = (cta >> 3) & 3;
    const int bb   = cta >> 5;
    const int tx0 = (tile & 1) * TW;
    const int ty0 = (tile >> 1) * TH;
    const int tid = threadIdx.x;
    const int px = tid & 31, pr = tid >> 5;
    const int gx = tx0 + px;
    const int gy0 = ty0 + pr;

    // BN constants (loop-invariant)
    float inv[8], off[8];
#pragma unroll
    for (int j = 0; j < 8; j++) {
        int f = fc * 8 + j;
        inv[j] = gamma[f] * rsqrtf(mvar[f] + BN_EPS);
        off[j] = beta[f] - mmean[f] * inv[j];
    }

    for (int t = 0; t < TT; t++) {
        unsigned long long acc0[16], acc1[16];
#pragma unroll
        for (int m = 0; m < 16; m++) { acc0[m] = 0ull; acc1[m] = 0ull; }

        if (t > 0) {
            // h tile read must bypass L1 (written by other SMs last step)
            const float* hin = g_h[(t + 1) & 1] + (size_t)bb * HH * WW * FF;
            load_input_tile<true>(s_in, hin, ty0, tx0, tid, FF);
            load_tap_lstm(s_w, Wh, 0, fc, tid);
            __syncthreads();

#pragma unroll
            for (int tap = 0; tap < 9; tap++) {
                if (tap < 8)
                    load_tap_lstm(&s_w[((tap + 1) & 1) * 1024], Wh, tap + 1, fc, tid);
                conv_tap(s_in, &s_w[(tap & 1) * 1024], pr, px, tap / 3, tap % 3,
                         acc0, acc1);
                __syncthreads();
            }
        }

        float a0[32], a1[32];
#pragma unroll
        for (int m = 0; m < 16; m++) {
            unpack2(acc0[m], a0[2 * m], a0[2 * m + 1]);
            unpack2(acc1[m], a1[2 * m], a1[2 * m + 1]);
        }

#pragma unroll
        for (int p = 0; p < 2; p++) {
            const float* a = p ? a1 : a0;
            const int gy = gy0 + p * 8;
            const size_t pix   = (size_t)bb * HH * WW + (size_t)gy * WW + gx;
            const size_t frame = (size_t)(bb * TT + t) * HH * WW + (size_t)gy * WW + gx;
            const float* xgp = &g_xg[frame * G4F];
            float* cst = &g_c[pix * FF + fc * 8];
            float* hst = &g_h[t & 1][pix * FF + fc * 8];
            float* op  = &out[frame * FF + fc * 8];

            float coldv[8] = {0,0,0,0,0,0,0,0};
            if (t > 0) {
                float4 c0 = ((const float4*)cst)[0];
                float4 c1 = ((const float4*)cst)[1];
                coldv[0]=c0.x; coldv[1]=c0.y; coldv[2]=c0.z; coldv[3]=c0.w;
                coldv[4]=c1.x; coldv[5]=c1.y; coldv[6]=c1.z; coldv[7]=c1.w;
            }

            float cv[8], hv[8], ov[8];
#pragma unroll
            for (int j = 0; j < 8; j++) {
                int f = fc * 8 + j;
                float gi = a[0 * 8 + j] + __ldg(&xgp[0 * 32 + f]);
                float gf = a[1 * 8 + j] + __ldg(&xgp[1 * 32 + f]);
                float gc = a[2 * 8 + j] + __ldg(&xgp[2 * 32 + f]);
                float go = a[3 * 8 + j] + __ldg(&xgp[3 * 32 + f]);
                gi = hsig(gi); gf = hsig(gf); go = hsig(go);
                float cn = gf * coldv[j] + gi * tanhf(gc);
                float h  = go * tanhf(cn);
                cv[j] = cn; hv[j] = h;
                ov[j] = fmaf(h, inv[j], off[j]);
            }
            ((float4*)cst)[0] = make_float4(cv[0], cv[1], cv[2], cv[3]);
            ((float4*)cst)[1] = make_float4(cv[4], cv[5], cv[6], cv[7]);
            ((float4*)hst)[0] = make_float4(hv[0], hv[1], hv[2], hv[3]);
            ((float4*)hst)[1] = make_float4(hv[4], hv[5], hv[6], hv[7]);
            ((float4*)op)[0]  = make_float4(ov[0], ov[1], ov[2], ov[3]);
            ((float4*)op)[1]  = make_float4(ov[4], ov[5], ov[6], ov[7]);
        }

        // Grid-wide barrier: h_t visible to all before step t+1
        if (t < TT - 1) {
            __threadfence();        // each thread publishes its h stores
            __syncthreads();
            if (tid == 0) {
                atomicAdd(&g_bar[t], 1u);
                while (*((volatile unsigned*)&g_bar[t]) < (unsigned)LSTM_GRID)
                    __nanosleep(64);
            }
            __syncthreads();
            __threadfence();        // acquire side
        }
    }
}

// ---------------------------------------------------------------------------
extern "C" void kernel_launch(void* const* d_in, const int* in_sizes, int n_in,
                              void* d_out, int out_size)
{
    const float* x     = (const float*)d_in[0];
    const float* Wx    = (const float*)d_in[1];
    const float* Wh    = (const float*)d_in[2];
    const float* b     = (const float*)d_in[3];
    const float* gamma = (const float*)d_in[4];
    const float* beta  = (const float*)d_in[5];
    const float* mmean = (const float*)d_in[6];
    const float* mvar  = (const float*)d_in[7];
    float* out = (float*)d_out;

    cudaFuncSetAttribute(xg_conv_kernel,
        cudaFuncAttributeMaxDynamicSharedMemorySize, SMEM_BYTES);
    cudaFuncSetAttribute(lstm_persistent,
        cudaFuncAttributeMaxDynamicSharedMemorySize, SMEM_BYTES);

    // 1) input-to-gate conv for all frames
    {
        dim3 grid(8, 4, BB * TT);
        xg_conv_kernel<<<grid, 256, SMEM_BYTES>>>(x, Wx, b);
    }
    // 2) reset barrier counters, then run all 16 steps in one launch
    bar_reset_kernel<<<1, 32>>>();
    lstm_persistent<<<LSTM_GRID, 256, SMEM_BYTES>>>(
        Wh, gamma, beta, mmean, mvar, out);
}